// round 14
// baseline (speedup 1.0000x reference)
#include <cuda_runtime.h>
#include <cuda_bf16.h>

// ---------------------------------------------------------------------------
// Decoder_65111704207909  (B=8192, T=20, H=128, K=5)
// Round 14: R12 base + pipe-complementary epilogue:
//   ff-gates (MUFU) -> heads-my (FMA, NO barrier between; h_my is phase-old)
//   -> bar -> heads-ff (240 fine slots). Sampling(t-1) stays in my-ch0 (R12).
// ---------------------------------------------------------------------------

#define Bsz 8192
#define Tt 20
#define Hh 128
#define KcK 5
#define NG 512                    // 4*H
#define ROWS 56
#define NCTA 147
#define NTHREADS 512
#define HSTR 68                   // phys row stride (272B; 16B-multiple)
#define CSTR 64                   // cond stride
#define KCH 32                    // k-rows per staged chunk
#define NCHUNK (Hh / KCH)         // 4
#define PRE_BB 16

typedef unsigned long long u64;

// enc_h @ W[:H] + b (bias folded), pair-packed: [(b>>1)][col][b&1]
__device__ float g_encW_my[(size_t)Bsz * NG];
__device__ float g_encW_ff[(size_t)Bsz * NG];
// U transposed: [k][j][gate]
__device__ float g_Ut_my[(size_t)Hh * NG];
__device__ float g_Ut_ff[(size_t)Hh * NG];
// Wh transposed: [c][k]
__device__ float g_Wht[75 * Hh];

__device__ __forceinline__ u64 pack2f(float x, float y) {
    u64 r; asm("mov.b64 %0, {%1, %2};" : "=l"(r) : "f"(x), "f"(y)); return r;
}
__device__ __forceinline__ u64 dup2f(float x) {
    u64 r; asm("mov.b64 %0, {%1, %1};" : "=l"(r) : "f"(x)); return r;
}
__device__ __forceinline__ void fma2(u64& d, u64 a, u64 b) {
    asm("fma.rn.f32x2 %0, %1, %2, %0;" : "+l"(d) : "l"(a), "l"(b));
}
__device__ __forceinline__ void unpack2(u64 v, float& x, float& y) {
    asm("mov.b64 {%0, %1}, %2;" : "=f"(x), "=f"(y) : "l"(v));
}

// ---- fast transcendentals ----
__device__ __forceinline__ float ex2f(float x) {
    float y; asm("ex2.approx.f32 %0, %1;" : "=f"(y) : "f"(x)); return y;
}
#define LOG2E 1.4426950408889634f
__device__ __forceinline__ float tanh_hw(float x) {
    float y; asm("tanh.approx.f32 %0, %1;" : "=f"(y) : "f"(x)); return y;
}
__device__ __forceinline__ float sigf(float x) {
    return fmaf(0.5f, tanh_hw(0.5f * x), 0.5f);   // 1 MUFU + 2 FMA
}
__device__ __forceinline__ float expf_fast(float x) { return ex2f(LOG2E * x); }

// logical row r (0..55) -> physical row: groups of 14 at pitch 16
__device__ __forceinline__ int physrow(int r) { return (r / 14) * 16 + (r % 14); }

// ---- cp.async: one chunk = KCH*NG = 16384 floats = 512 thr x 8 x 16B ----
__device__ __forceinline__ void stage_chunk(float* dst, const float* __restrict__ src, int tid) {
    unsigned smp = (unsigned)__cvta_generic_to_shared(dst);
#pragma unroll
    for (int i = 0; i < 8; i++) {
        asm volatile("cp.async.cg.shared.global [%0], [%1], 16;"
                     :: "r"(smp + (unsigned)((tid + i * NTHREADS) * 16)),
                        "l"(src + (size_t)(tid + i * NTHREADS) * 4)
                     : "memory");
    }
    asm volatile("cp.async.commit_group;" ::: "memory");
}
template <int N>
__device__ __forceinline__ void cp_wait() {
    asm volatile("cp.async.wait_group %0;" :: "n"(N) : "memory");
}

// ---------------------------------------------------------------------------
// Sampling context (constant per thread)
// ---------------------------------------------------------------------------
struct SampCtx {
    const float *cond_m, *cond_y, *cond_f, *cond_fa, *gumbel, *znorm;
    float *out_gm, *out_gy, *out_gf, *out_gfa;
    float *sh_r, *sh_cond5, *sh_cond2, *scratch;
    int s_row, s_d, s_b, s_pr, sbase;
    bool s_act, s_valid;
};

// prefetch sampling inputs for step s into smem scratch (9 floats/thread)
__device__ __forceinline__ void prefetch_exec(const SampCtx& C, int s) {
    if (!C.s_act) return;
    const int tn = min(s + 1, Tt - 1);
    const float* gum = C.gumbel + (((size_t)s * 4 + C.s_d) * Bsz + C.s_b) * KcK;
    const float* zn  = C.znorm + ((size_t)s * Bsz + C.s_b) * 5;
    float v[9];
#pragma unroll
    for (int k = 0; k < 5; k++) v[k] = __ldg(gum + k);
    v[6] = 0.f; v[8] = 0.f;
    if (C.s_d == 0) {
        v[5] = __ldg(zn + 0); v[6] = __ldg(zn + 1);
        v[7] = __ldg(&C.cond_m[((size_t)C.s_b * Tt + tn) * 2 + 0]);
        v[8] = __ldg(&C.cond_m[((size_t)C.s_b * Tt + tn) * 2 + 1]);
    } else if (C.s_d == 1) {
        v[5] = __ldg(zn + 2); v[7] = __ldg(&C.cond_y[(size_t)C.s_b * Tt + tn]);
    } else if (C.s_d == 2) {
        v[5] = __ldg(zn + 3); v[7] = __ldg(&C.cond_f[(size_t)C.s_b * Tt + tn]);
    } else {
        v[5] = __ldg(zn + 4); v[7] = __ldg(&C.cond_fa[(size_t)C.s_b * Tt + tn]);
    }
#pragma unroll
    for (int i = 0; i < 9; i++) C.scratch[C.sbase + i] = v[i];
}

// execute sampling for step s (inputs in scratch, heads results in sh_r)
__device__ __forceinline__ void sample_exec(const SampCtx& C, int s) {
    if (!C.s_act) return;
    float v[9];
#pragma unroll
    for (int i = 0; i < 9; i++) v[i] = C.scratch[C.sbase + i];
    const float pz1 = v[5], pz2 = v[6], pn1 = v[7], pn2 = v[8];
    const int row = C.s_row, pr = C.s_pr, d = C.s_d, b = C.s_b;

    if (d == 0) {
        const float* rb = C.sh_r + row * 76;
        float lg[5], mul[5], sl[5], mulat[5], slat[5], rho[5];
#pragma unroll
        for (int k = 0; k < 5; k++) {
            lg[k]    = rb[k];
            mul[k]   = rb[5 + k];
            sl[k]    = expf_fast(rb[10 + k]);
            mulat[k] = rb[15 + k];
            slat[k]  = expf_fast(rb[20 + k]);
            rho[k]   = tanh_hw(rb[25 + k]);
        }
        float mx = lg[0];
#pragma unroll
        for (int k = 1; k < 5; k++) mx = fmaxf(mx, lg[k]);
        float am[5], ssum = 0.0f;
#pragma unroll
        for (int k = 0; k < 5; k++) { am[k] = expf_fast(lg[k] - mx); ssum += am[k]; }
        float inv = 1.0f / ssum;
#pragma unroll
        for (int k = 0; k < 5; k++) am[k] *= inv;
        int im = 0; float best = lg[0] + v[0];
#pragma unroll
        for (int k = 1; k < 5; k++) {
            float t2 = lg[k] + v[k];
            if (t2 > best) { best = t2; im = k; }
        }
        float rr = rho[im];
        float s_long = mul[im] + sl[im] * pz1;
        float s_lt = mulat[im] + slat[im] * (rr * pz1 + sqrtf(fmaxf(1.0f - rr * rr, 0.0f)) * pz2);
        C.sh_cond5[0 * CSTR + pr] = (fabsf(s_long - pn1) < 0.3f) ? s_long : pn1;
        C.sh_cond5[1 * CSTR + pr] = (fabsf(s_lt  - pn2) < 0.1f) ? s_lt  : pn2;
        if (C.s_valid) {
            float* o = C.out_gm + ((size_t)b * Tt + s) * 30;
#pragma unroll
            for (int k = 0; k < 5; k++) {
                o[k] = am[k]; o[5 + k] = mul[k]; o[10 + k] = sl[k];
                o[15 + k] = mulat[k]; o[20 + k] = slat[k]; o[25 + k] = rho[k];
            }
        }
    } else {
        const float* rb;
        float* osec;
        if (d == 1)      { rb = C.sh_r + row * 76 + 30; osec = C.out_gy; }
        else if (d == 2) { rb = C.sh_r + row * 76 + 45; osec = C.out_gf; }
        else             { rb = C.sh_r + row * 76 + 60; osec = C.out_gfa; }
        float lg[5], mu[5], sg[5];
#pragma unroll
        for (int k = 0; k < 5; k++) {
            lg[k] = rb[k]; mu[k] = rb[5 + k]; sg[k] = expf_fast(rb[10 + k]);
        }
        float mx = lg[0];
#pragma unroll
        for (int k = 1; k < 5; k++) mx = fmaxf(mx, lg[k]);
        float am[5], ssum = 0.0f;
#pragma unroll
        for (int k = 0; k < 5; k++) { am[k] = expf_fast(lg[k] - mx); ssum += am[k]; }
        float inv = 1.0f / ssum;
#pragma unroll
        for (int k = 0; k < 5; k++) am[k] *= inv;
        int im = 0; float best = lg[0] + v[0];
#pragma unroll
        for (int k = 1; k < 5; k++) {
            float t2 = lg[k] + v[k];
            if (t2 > best) { best = t2; im = k; }
        }
        float samp = mu[im] + sg[im] * pz1;
        float cn = (fabsf(samp - pn1) < 0.3f) ? samp : pn1;
        if (d == 1) {
            C.sh_cond5[2 * CSTR + pr] = cn;
        } else if (d == 2) {
            C.sh_cond5[3 * CSTR + pr] = cn;
            C.sh_cond2[0 * CSTR + pr] = cn;
        } else {
            C.sh_cond5[4 * CSTR + pr] = cn;
            C.sh_cond2[1 * CSTR + pr] = cn;
        }
        if (C.s_valid) {
            float* o = osec + ((size_t)b * Tt + s) * 15;
#pragma unroll
            for (int k = 0; k < 5; k++) {
                o[k] = am[k]; o[5 + k] = mu[k]; o[10 + k] = sg[k];
            }
        }
    }
}

// ---------------------------------------------------------------------------
// Precompute: g_encW = state_h @ W[:H,:] + b (pair-packed) + folded transposes
// ---------------------------------------------------------------------------
__global__ __launch_bounds__(256) void precompute_kernel(
    const float* __restrict__ state_h,
    const float* __restrict__ W_my, const float* __restrict__ b_my,
    const float* __restrict__ W_ff, const float* __restrict__ b_ff,
    const float* __restrict__ U_my, const float* __restrict__ U_ff,
    const float* __restrict__ Wh_my, const float* __restrict__ Wh_ff)
{
    const int t = threadIdx.x;

    // folded transposes (blocks 0..255 cover Hh*NG = 65536 elems)
    {
        int gidx = blockIdx.x * 256 + t;
        if (gidx < Hh * NG) {
            int k = gidx >> 9;
            int r = gidx & 511;
            int j = r >> 2, g = r & 3;
            g_Ut_my[gidx] = U_my[(size_t)k * NG + g * 128 + j];
            g_Ut_ff[gidx] = U_ff[(size_t)k * NG + g * 128 + j];
        }
        if (gidx < 75 * Hh) {
            int c = gidx >> 7, k = gidx & 127;
            g_Wht[gidx] = (c < 45) ? Wh_my[(size_t)k * 45 + c]
                                   : Wh_ff[(size_t)k * 30 + (c - 45)];
        }
    }

    __shared__ float hsh[Hh * PRE_BB];  // [k][bb]
    const int b0 = blockIdx.x * PRE_BB;

    for (int idx = t; idx < Hh * PRE_BB; idx += 256) {
        int k = idx / PRE_BB, bb = idx % PRE_BB;
        hsh[idx] = state_h[(size_t)(b0 + bb) * Hh + k];
    }
    __syncthreads();

    const int c0 = 2 * t;
    u64 accm[PRE_BB], accf[PRE_BB];
    u64 bm = pack2f(b_my[c0], b_my[c0 + 1]);
    u64 bf = pack2f(b_ff[c0], b_ff[c0 + 1]);
#pragma unroll
    for (int bb = 0; bb < PRE_BB; bb++) { accm[bb] = bm; accf[bb] = bf; }

    for (int k = 0; k < Hh; k++) {
        u64 wm = *(const u64*)&W_my[(size_t)k * NG + c0];
        u64 wf = *(const u64*)&W_ff[(size_t)k * NG + c0];
#pragma unroll
        for (int bb = 0; bb < PRE_BB; bb++) {
            u64 hh = dup2f(hsh[k * PRE_BB + bb]);
            fma2(accm[bb], hh, wm);
            fma2(accf[bb], hh, wf);
        }
    }
    // pair-packed store: idx = ((b>>1)*NG + col)*2 + (b&1)
#pragma unroll
    for (int bb = 0; bb < PRE_BB; bb++) {
        int b = b0 + bb;
        size_t base = ((size_t)(b >> 1) * NG) * 2 + (b & 1);
        float v0, v1;
        unpack2(accm[bb], v0, v1);
        g_encW_my[base + 2 * (size_t)c0] = v0;
        g_encW_my[base + 2 * (size_t)(c0 + 1)] = v1;
        unpack2(accf[bb], v0, v1);
        g_encW_ff[base + 2 * (size_t)c0] = v0;
        g_encW_ff[base + 2 * (size_t)(c0 + 1)] = v1;
    }
}

// ---------------------------------------------------------------------------
// One LSTM update for 56 rows, 512 threads, rotated chunk order.
// SAMP phases run sampling(t-1) + prefetch(t) inside the ch0 window.
// acc encW init at ch0 (after the hidden work); cond-tail at ch1.
// ---------------------------------------------------------------------------
template <int NQ, bool SAMP>
__device__ __forceinline__ void lstm_phase(
    const float* __restrict__ encW,   // pair-packed
    const float* __restrict__ Ut,     // gate-interleaved [k][j][gate]
    const float* __restrict__ Wg,     // W matrix (tail rows H.. used)
    const float* __restrict__ pre_src,// next phase's Ut
    const float* sh_cond, float* sh_h, float* sh_U,
    float (&c)[14], int j, int rphys, const int* epair, int tid, int rot,
    const SampCtx* sc, int t)
{
    u64 acc[4][7];

#pragma unroll
    for (int ch = 0; ch < NCHUNK; ch++) {
        const int pch = (ch + rot) & (NCHUNK - 1);
        cp_wait<0>();
        __syncthreads();   // chunk visible; all warps past previous compute
        if (ch + 1 < NCHUNK) {
            const int pnx = (ch + 1 + rot) & (NCHUNK - 1);
            stage_chunk(sh_U + ((ch + 1) & 1) * KCH * NG,
                        Ut + (size_t)pnx * KCH * NG, tid);
        } else {
            stage_chunk(sh_U + ((ch + 1) & 1) * KCH * NG,
                        pre_src + (size_t)rot * KCH * NG, tid);
        }
        if (ch == 0) {
            if (SAMP) {
                if (t > 0) sample_exec(*sc, t - 1);
                prefetch_exec(*sc, t);
            }
            // acc init: encW (bias folded, LDG.64)
#pragma unroll
            for (int g4 = 0; g4 < 4; g4++) {
                const int col = g4 * 128 + j;
#pragma unroll
                for (int p = 0; p < 7; p++)
                    acc[g4][p] = *(const u64*)&encW[((size_t)epair[p] * NG + col) * 2];
            }
        }
        if (ch == 1) {
            // cond-tail (sampling's cond writes ordered by this chunk's barrier)
#pragma unroll
            for (int q = 0; q < NQ; q++) {
                u64 cpp[7];
#pragma unroll
                for (int p = 0; p < 7; p++)
                    cpp[p] = *(const u64*)(sh_cond + q * CSTR + rphys + 2 * p);
#pragma unroll
                for (int g4 = 0; g4 < 4; g4++) {
                    u64 wd = dup2f(__ldg(&Wg[(size_t)(Hh + q) * NG + g4 * 128 + j]));
#pragma unroll
                    for (int p = 0; p < 7; p++) fma2(acc[g4][p], cpp[p], wd);
                }
            }
        }
        const float* ub = sh_U + (ch & 1) * KCH * NG + 4 * j;
        const float* hb = sh_h + (pch * KCH) * HSTR + rphys;
#pragma unroll
        for (int kk = 0; kk < KCH; kk++) {
            float4 uu = *(const float4*)(ub + kk * NG);
            u64 u0 = dup2f(uu.x);
            u64 u1 = dup2f(uu.y);
            u64 u2 = dup2f(uu.z);
            u64 u3 = dup2f(uu.w);
            const float* hk = hb + kk * HSTR;
            ulonglong2 h01 = *(const ulonglong2*)(hk);
            ulonglong2 h23 = *(const ulonglong2*)(hk + 4);
            ulonglong2 h45 = *(const ulonglong2*)(hk + 8);
            u64 h6 = *(const u64*)(hk + 12);
            u64 hp[7] = { h01.x, h01.y, h23.x, h23.y, h45.x, h45.y, h6 };
#pragma unroll
            for (int p = 0; p < 7; p++) {
                u64 h2 = hp[p];
                fma2(acc[0][p], h2, u0);
                fma2(acc[1][p], h2, u1);
                fma2(acc[2][p], h2, u2);
                fma2(acc[3][p], h2, u3);
            }
        }
    }
    __syncthreads();  // all threads done reading old sh_h

    // ---- gates; c register-private; HW tanh ----
#pragma unroll
    for (int p = 0; p < 7; p++) {
        float zi0, zi1, zf0, zf1, zg0, zg1, zo0, zo1;
        unpack2(acc[0][p], zi0, zi1);
        unpack2(acc[1][p], zf0, zf1);
        unpack2(acc[2][p], zg0, zg1);
        unpack2(acc[3][p], zo0, zo1);
        float c20 = sigf(zf0) * c[2 * p]     + sigf(zi0) * tanh_hw(zg0);
        float c21 = sigf(zf1) * c[2 * p + 1] + sigf(zi1) * tanh_hw(zg1);
        c[2 * p] = c20; c[2 * p + 1] = c21;
        *(u64*)(sh_h + j * HSTR + rphys + 2 * p) =
            pack2f(sigf(zo0) * tanh_hw(c20), sigf(zo1) * tanh_hw(c21));
    }
}

// ---------------------------------------------------------------------------
__global__ __launch_bounds__(NTHREADS, 1) void decoder_kernel(
    const float* __restrict__ cond_m, const float* __restrict__ cond_y,
    const float* __restrict__ cond_f, const float* __restrict__ cond_fa,
    const float* __restrict__ state_h, const float* __restrict__ state_c,
    const float* __restrict__ W_my, const float* __restrict__ W_ff,
    const float* __restrict__ bh_my, const float* __restrict__ bh_ff,
    const float* __restrict__ gumbel, const float* __restrict__ znorm,
    float* __restrict__ out)
{
    extern __shared__ float smem[];
    float* sh_U     = smem;                       // 2*KCH*NG = 32768 floats
    float* sh_h_my  = sh_U + 2 * KCH * NG;        // Hh*HSTR
    float* sh_h_ff  = sh_h_my + Hh * HSTR;
    float* sh_cond5 = sh_h_ff + Hh * HSTR;        // [q][CSTR] phys rows
    float* sh_cond2 = sh_cond5 + 5 * CSTR;
    float* sh_r     = sh_cond2 + 2 * CSTR;        // [logical row][76]
    float* scratch  = sh_r + ROWS * 76;           // 4*ROWS*9 sampling inputs

    const int tid = threadIdx.x;
    const int rowbase = blockIdx.x * ROWS;
    const int rot = blockIdx.x & (NCHUNK - 1);
    const int j = tid & 127;
    const int g = tid >> 7;        // 0..3
    const int rlog = g * 14;
    const int rphys = g * 16;

    // ---- init h and cond ----
    for (int idx = tid; idx < Hh * ROWS; idx += NTHREADS) {
        int k = idx / ROWS, row = idx % ROWS;
        int b = min(rowbase + row, Bsz - 1);
        float hv = state_h[(size_t)b * Hh + k];
        int pr = physrow(row);
        sh_h_my[k * HSTR + pr] = hv;
        sh_h_ff[k * HSTR + pr] = hv;
    }
    if (tid < ROWS) {
        int row = tid;
        int pr = physrow(row);
        int b = min(rowbase + row, Bsz - 1);
        float m0 = cond_m[((size_t)b * Tt) * 2 + 0];
        float m1 = cond_m[((size_t)b * Tt) * 2 + 1];
        float y0 = cond_y[(size_t)b * Tt];
        float f0 = cond_f[(size_t)b * Tt];
        float a0 = cond_fa[(size_t)b * Tt];
        sh_cond5[0 * CSTR + pr] = m0;
        sh_cond5[1 * CSTR + pr] = m1;
        sh_cond5[2 * CSTR + pr] = y0;
        sh_cond5[3 * CSTR + pr] = f0;
        sh_cond5[4 * CSTR + pr] = a0;
        sh_cond2[0 * CSTR + pr] = f0;
        sh_cond2[1 * CSTR + pr] = a0;
    }

    // ---- c state in registers, encW pair indices (logical rows) ----
    float cmy[14], cff[14];
    int epair[7];
#pragma unroll
    for (int r = 0; r < 14; r++) {
        int b = min(rowbase + rlog + r, Bsz - 1);
        float cv = state_c[(size_t)b * Hh + j];
        cmy[r] = cv; cff[r] = cv;
    }
#pragma unroll
    for (int p = 0; p < 7; p++)
        epair[p] = min(rowbase + rlog + 2 * p, Bsz - 2) >> 1;

    // heads-my (no-barrier block): 300-map threads with col<45 -> 180 active
    const int hmc = tid % 75;
    const int hmq = tid / 75;
    const bool hmy_act = (tid < 300) && (hmc < 45);
    const float hmy_bias = hmy_act ? bh_my[hmc] : 0.0f;

    // heads-ff (post-barrier): 240 fine slots, col 45+tid%30, subgroup tid/30
    const bool hff_act = tid < 240;
    const int hff_c = 45 + (tid % 30);
    const int hff_sub = tid / 30;      // 0..7
    const float hff_bias = hff_act ? bh_ff[hff_c - 45] : 0.0f;

    // sampling context
    SampCtx ctx;
    ctx.cond_m = cond_m; ctx.cond_y = cond_y; ctx.cond_f = cond_f;
    ctx.cond_fa = cond_fa; ctx.gumbel = gumbel; ctx.znorm = znorm;
    ctx.out_gm = out;
    ctx.out_gy = out + (size_t)Bsz * Tt * 30;
    ctx.out_gf = out + (size_t)Bsz * Tt * 45;
    ctx.out_gfa = out + (size_t)Bsz * Tt * 60;
    ctx.sh_r = sh_r; ctx.sh_cond5 = sh_cond5; ctx.sh_cond2 = sh_cond2;
    ctx.scratch = scratch;
    ctx.s_row = tid >> 2;
    ctx.s_d = tid & 3;
    ctx.s_act = tid < 4 * ROWS;
    ctx.s_b = ctx.s_act ? min(rowbase + ctx.s_row, Bsz - 1) : 0;
    ctx.s_valid = ctx.s_act && (rowbase + ctx.s_row) < Bsz;
    ctx.s_pr = physrow(min(ctx.s_row, ROWS - 1));
    ctx.sbase = tid * 9;

    __syncthreads();

    // stage my-phase chunk `rot` for step 0 (buffer 0)
    stage_chunk(sh_U, g_Ut_my + (size_t)rot * KCH * NG, tid);

    for (int t = 0; t < Tt; t++) {
        lstm_phase<5, true>(g_encW_my, g_Ut_my, W_my, g_Ut_ff,
                            sh_cond5, sh_h_my, sh_U, cmy, j, rphys, epair,
                            tid, rot, &ctx, t);
        lstm_phase<2, false>(g_encW_ff, g_Ut_ff, W_ff, g_Ut_my,
                             sh_cond2, sh_h_ff, sh_U, cff, j, rphys, epair,
                             tid, rot, &ctx, t);
        // NOTE: no barrier here. ff-gates (MUFU) just ran; heads-my (FMA)
        // reads h_my written one phase ago (ordered by ff's chunk barriers),
        // so the two blocks overlap on complementary pipes across warps.

        // ===== heads-my: 45 cols x 4 quarters (180 threads, 7 pairs) =====
        if (hmy_act) {
            const float* hb = sh_h_my + hmq * 16;
            const float4* wr = (const float4*)(g_Wht + hmc * Hh);
            u64 a[7];
            u64 binit = dup2f(hmy_bias);
#pragma unroll
            for (int p = 0; p < 7; p++) a[p] = binit;
#pragma unroll 4
            for (int k4 = 0; k4 < Hh / 4; k4++) {
                float4 w4 = __ldg(&wr[k4]);
                float wv[4] = { w4.x, w4.y, w4.z, w4.w };
#pragma unroll
                for (int kk = 0; kk < 4; kk++) {
                    const float* hk = hb + (4 * k4 + kk) * HSTR;
                    ulonglong2 h01 = *(const ulonglong2*)(hk);
                    ulonglong2 h23 = *(const ulonglong2*)(hk + 4);
                    ulonglong2 h45 = *(const ulonglong2*)(hk + 8);
                    u64 h6 = *(const u64*)(hk + 12);
                    u64 wd = dup2f(wv[kk]);
                    fma2(a[0], h01.x, wd);
                    fma2(a[1], h01.y, wd);
                    fma2(a[2], h23.x, wd);
                    fma2(a[3], h23.y, wd);
                    fma2(a[4], h45.x, wd);
                    fma2(a[5], h45.y, wd);
                    fma2(a[6], h6, wd);
                }
            }
#pragma unroll
            for (int p = 0; p < 7; p++) {
                float v0, v1;
                unpack2(a[p], v0, v1);
                int row = hmq * 14 + 2 * p;
                sh_r[row * 76 + hmc] = v0;
                sh_r[(row + 1) * 76 + hmc] = v1;
            }
        }
        __syncthreads();   // h_ff (ff-gates) visible for heads-ff

        // ===== heads-ff: 240 fine slots (30 cols x 8 subgroups of 8 rows) ====
        if (hff_act) {
            const float* hb = sh_h_ff + hff_sub * 8;
            const float4* wr = (const float4*)(g_Wht + hff_c * Hh);
            u64 a0, a1, a2, a3;
            a0 = a1 = a2 = a3 = dup2f(hff_bias);
#pragma unroll 4
            for (int k4 = 0; k4 < Hh / 4; k4++) {
                float4 w4 = __ldg(&wr[k4]);
                float wv[4] = { w4.x, w4.y, w4.z, w4.w };
#pragma unroll
                for (int kk = 0; kk < 4; kk++) {
                    const float* hk = hb + (4 * k4 + kk) * HSTR;
                    ulonglong2 hA = *(const ulonglong2*)(hk);
                    ulonglong2 hB = *(const ulonglong2*)(hk + 4);
                    u64 wd = dup2f(wv[kk]);
                    fma2(a0, hA.x, wd);
                    fma2(a1, hA.y, wd);
                    fma2(a2, hB.x, wd);
                    fma2(a3, hB.y, wd);
                }
            }
            float v[8];
            unpack2(a0, v[0], v[1]);
            unpack2(a1, v[2], v[3]);
            unpack2(a2, v[4], v[5]);
            unpack2(a3, v[6], v[7]);
#pragma unroll
            for (int i = 0; i < 8; i++) {
                int p = hff_sub * 8 + i;
                int r16 = p & 15;
                if (r16 < 14)
                    sh_r[((p >> 4) * 14 + r16) * 76 + hff_c] = v[i];
            }
        }
        // no trailing barrier: next my-phase ch0 barrier orders sh_r
    }

    __syncthreads();              // sh_r(T-1) visible
    sample_exec(ctx, Tt - 1);     // final step's sampling/outputs
}

// ---------------------------------------------------------------------------
extern "C" void kernel_launch(void* const* d_in, const int* in_sizes, int n_in,
                              void* d_out, int out_size)
{
    (void)in_sizes; (void)n_in; (void)out_size;
    const float* cond_m  = (const float*)d_in[0];
    const float* cond_y  = (const float*)d_in[1];
    const float* cond_f  = (const float*)d_in[2];
    const float* cond_fa = (const float*)d_in[3];
    const float* state_h = (const float*)d_in[4];
    const float* state_c = (const float*)d_in[5];
    const float* W_my    = (const float*)d_in[6];
    const float* U_my    = (const float*)d_in[7];
    const float* b_my    = (const float*)d_in[8];
    const float* W_ff    = (const float*)d_in[9];
    const float* U_ff    = (const float*)d_in[10];
    const float* b_ff    = (const float*)d_in[11];
    const float* Wh_my   = (const float*)d_in[12];
    const float* bh_my   = (const float*)d_in[13];
    const float* Wh_ff   = (const float*)d_in[14];
    const float* bh_ff   = (const float*)d_in[15];
    const float* gumbel  = (const float*)d_in[16];
    const float* znorm   = (const float*)d_in[17];
    float* out = (float*)d_out;

    const int smem_floats = 2 * KCH * NG + 2 * Hh * HSTR + 7 * CSTR + ROWS * 76
                            + 4 * ROWS * 9;
    const int smem_bytes = smem_floats * (int)sizeof(float);  // 227584 B

    cudaFuncSetAttribute(decoder_kernel,
                         cudaFuncAttributeMaxDynamicSharedMemorySize, smem_bytes);

    precompute_kernel<<<Bsz / PRE_BB, 256>>>(state_h, W_my, b_my, W_ff, b_ff,
                                             U_my, U_ff, Wh_my, Wh_ff);
    decoder_kernel<<<NCTA, NTHREADS, smem_bytes>>>(
        cond_m, cond_y, cond_f, cond_fa, state_h, state_c,
        W_my, W_ff, bh_my, bh_ff, gumbel, znorm, out);
}

// round 15
// speedup vs baseline: 1.0175x; 1.0175x over previous
#include <cuda_runtime.h>
#include <cuda_bf16.h>

// ---------------------------------------------------------------------------
// Decoder_65111704207909  (B=8192, T=20, H=128, K=5)
// Round 15: R12 base + band-local GEMM pipeline:
//  - band b = (tid>>5)&3: 4 warps, same SMSP, reads U floats [128b,128b+128)
//  - each band stages its own chunk slice; per-chunk sync = bar.sync b+1,128
//  - full barriers only at: post-my-loop, post-ff-loop, pre-heads, post-heads
//  - sampling(t-1) hidden in my-ch0; my cond-tail post-loop; ff cond-tail ch1
// ---------------------------------------------------------------------------

#define Bsz 8192
#define Tt 20
#define Hh 128
#define KcK 5
#define NG 512                    // 4*H
#define ROWS 56
#define NCTA 147
#define NTHREADS 512
#define HSTR 68                   // phys row stride
#define CSTR 64                   // cond stride
#define KCH 32                    // k-rows per staged chunk
#define NCHUNK (Hh / KCH)         // 4
#define PRE_BB 16

typedef unsigned long long u64;

__device__ float g_encW_my[(size_t)Bsz * NG];   // pair-packed enc@W + b
__device__ float g_encW_ff[(size_t)Bsz * NG];
__device__ float g_Ut_my[(size_t)Hh * NG];      // [k][j][gate]
__device__ float g_Ut_ff[(size_t)Hh * NG];
__device__ float g_Wht[75 * Hh];                // [c][k]

__device__ __forceinline__ u64 pack2f(float x, float y) {
    u64 r; asm("mov.b64 %0, {%1, %2};" : "=l"(r) : "f"(x), "f"(y)); return r;
}
__device__ __forceinline__ u64 dup2f(float x) {
    u64 r; asm("mov.b64 %0, {%1, %1};" : "=l"(r) : "f"(x)); return r;
}
__device__ __forceinline__ void fma2(u64& d, u64 a, u64 b) {
    asm("fma.rn.f32x2 %0, %1, %2, %0;" : "+l"(d) : "l"(a), "l"(b));
}
__device__ __forceinline__ void unpack2(u64 v, float& x, float& y) {
    asm("mov.b64 {%0, %1}, %2;" : "=f"(x), "=f"(y) : "l"(v));
}
__device__ __forceinline__ float ex2f(float x) {
    float y; asm("ex2.approx.f32 %0, %1;" : "=f"(y) : "f"(x)); return y;
}
#define LOG2E 1.4426950408889634f
__device__ __forceinline__ float tanh_hw(float x) {
    float y; asm("tanh.approx.f32 %0, %1;" : "=f"(y) : "f"(x)); return y;
}
__device__ __forceinline__ float sigf(float x) {
    return fmaf(0.5f, tanh_hw(0.5f * x), 0.5f);
}
__device__ __forceinline__ float expf_fast(float x) { return ex2f(LOG2E * x); }

__device__ __forceinline__ int physrow(int r) { return (r / 14) * 16 + (r % 14); }

// band-local chunk staging: 128 threads stage 32 rows x 128 floats (their band)
__device__ __forceinline__ void stage_band(float* dstbuf, const float* __restrict__ src,
                                           int boff, int ib) {
    unsigned smp = (unsigned)__cvta_generic_to_shared(dstbuf + boff);
    const float* s = src + boff;
#pragma unroll
    for (int i = 0; i < 8; i++) {
        int idx = ib + i * 128;          // 0..1023
        int k = idx >> 5;                // 0..31
        int f4 = idx & 31;               // float4 within band row
        asm volatile("cp.async.cg.shared.global [%0], [%1], 16;"
                     :: "r"(smp + (unsigned)((k * NG + f4 * 4) * 4)),
                        "l"(s + (size_t)k * NG + f4 * 4)
                     : "memory");
    }
    asm volatile("cp.async.commit_group;" ::: "memory");
}
template <int N>
__device__ __forceinline__ void cp_wait() {
    asm volatile("cp.async.wait_group %0;" :: "n"(N) : "memory");
}
__device__ __forceinline__ void band_bar(int band) {
    asm volatile("bar.sync %0, 128;" :: "r"(band + 1) : "memory");
}

// ---------------------------------------------------------------------------
struct SampCtx {
    const float *cond_m, *cond_y, *cond_f, *cond_fa, *gumbel, *znorm;
    float *out_gm, *out_gy, *out_gf, *out_gfa;
    float *sh_r, *sh_cond5, *sh_cond2, *scratch;
    int s_row, s_d, s_b, s_pr, sbase;
    bool s_act, s_valid;
};

__device__ __forceinline__ void prefetch_exec(const SampCtx& C, int s) {
    if (!C.s_act) return;
    const int tn = min(s + 1, Tt - 1);
    const float* gum = C.gumbel + (((size_t)s * 4 + C.s_d) * Bsz + C.s_b) * KcK;
    const float* zn  = C.znorm + ((size_t)s * Bsz + C.s_b) * 5;
    float v[9];
#pragma unroll
    for (int k = 0; k < 5; k++) v[k] = __ldg(gum + k);
    v[6] = 0.f; v[8] = 0.f;
    if (C.s_d == 0) {
        v[5] = __ldg(zn + 0); v[6] = __ldg(zn + 1);
        v[7] = __ldg(&C.cond_m[((size_t)C.s_b * Tt + tn) * 2 + 0]);
        v[8] = __ldg(&C.cond_m[((size_t)C.s_b * Tt + tn) * 2 + 1]);
    } else if (C.s_d == 1) {
        v[5] = __ldg(zn + 2); v[7] = __ldg(&C.cond_y[(size_t)C.s_b * Tt + tn]);
    } else if (C.s_d == 2) {
        v[5] = __ldg(zn + 3); v[7] = __ldg(&C.cond_f[(size_t)C.s_b * Tt + tn]);
    } else {
        v[5] = __ldg(zn + 4); v[7] = __ldg(&C.cond_fa[(size_t)C.s_b * Tt + tn]);
    }
#pragma unroll
    for (int i = 0; i < 9; i++) C.scratch[C.sbase + i] = v[i];
}

__device__ __forceinline__ void sample_exec(const SampCtx& C, int s) {
    if (!C.s_act) return;
    float v[9];
#pragma unroll
    for (int i = 0; i < 9; i++) v[i] = C.scratch[C.sbase + i];
    const float pz1 = v[5], pz2 = v[6], pn1 = v[7], pn2 = v[8];
    const int row = C.s_row, pr = C.s_pr, d = C.s_d, b = C.s_b;

    if (d == 0) {
        const float* rb = C.sh_r + row * 76;
        float lg[5], mul[5], sl[5], mulat[5], slat[5], rho[5];
#pragma unroll
        for (int k = 0; k < 5; k++) {
            lg[k]    = rb[k];
            mul[k]   = rb[5 + k];
            sl[k]    = expf_fast(rb[10 + k]);
            mulat[k] = rb[15 + k];
            slat[k]  = expf_fast(rb[20 + k]);
            rho[k]   = tanh_hw(rb[25 + k]);
        }
        float mx = lg[0];
#pragma unroll
        for (int k = 1; k < 5; k++) mx = fmaxf(mx, lg[k]);
        float am[5], ssum = 0.0f;
#pragma unroll
        for (int k = 0; k < 5; k++) { am[k] = expf_fast(lg[k] - mx); ssum += am[k]; }
        float inv = 1.0f / ssum;
#pragma unroll
        for (int k = 0; k < 5; k++) am[k] *= inv;
        int im = 0; float best = lg[0] + v[0];
#pragma unroll
        for (int k = 1; k < 5; k++) {
            float t2 = lg[k] + v[k];
            if (t2 > best) { best = t2; im = k; }
        }
        float rr = rho[im];
        float s_long = mul[im] + sl[im] * pz1;
        float s_lt = mulat[im] + slat[im] * (rr * pz1 + sqrtf(fmaxf(1.0f - rr * rr, 0.0f)) * pz2);
        C.sh_cond5[0 * CSTR + pr] = (fabsf(s_long - pn1) < 0.3f) ? s_long : pn1;
        C.sh_cond5[1 * CSTR + pr] = (fabsf(s_lt  - pn2) < 0.1f) ? s_lt  : pn2;
        if (C.s_valid) {
            float* o = C.out_gm + ((size_t)b * Tt + s) * 30;
#pragma unroll
            for (int k = 0; k < 5; k++) {
                o[k] = am[k]; o[5 + k] = mul[k]; o[10 + k] = sl[k];
                o[15 + k] = mulat[k]; o[20 + k] = slat[k]; o[25 + k] = rho[k];
            }
        }
    } else {
        const float* rb;
        float* osec;
        if (d == 1)      { rb = C.sh_r + row * 76 + 30; osec = C.out_gy; }
        else if (d == 2) { rb = C.sh_r + row * 76 + 45; osec = C.out_gf; }
        else             { rb = C.sh_r + row * 76 + 60; osec = C.out_gfa; }
        float lg[5], mu[5], sg[5];
#pragma unroll
        for (int k = 0; k < 5; k++) {
            lg[k] = rb[k]; mu[k] = rb[5 + k]; sg[k] = expf_fast(rb[10 + k]);
        }
        float mx = lg[0];
#pragma unroll
        for (int k = 1; k < 5; k++) mx = fmaxf(mx, lg[k]);
        float am[5], ssum = 0.0f;
#pragma unroll
        for (int k = 0; k < 5; k++) { am[k] = expf_fast(lg[k] - mx); ssum += am[k]; }
        float inv = 1.0f / ssum;
#pragma unroll
        for (int k = 0; k < 5; k++) am[k] *= inv;
        int im = 0; float best = lg[0] + v[0];
#pragma unroll
        for (int k = 1; k < 5; k++) {
            float t2 = lg[k] + v[k];
            if (t2 > best) { best = t2; im = k; }
        }
        float samp = mu[im] + sg[im] * pz1;
        float cn = (fabsf(samp - pn1) < 0.3f) ? samp : pn1;
        if (d == 1) {
            C.sh_cond5[2 * CSTR + pr] = cn;
        } else if (d == 2) {
            C.sh_cond5[3 * CSTR + pr] = cn;
            C.sh_cond2[0 * CSTR + pr] = cn;
        } else {
            C.sh_cond5[4 * CSTR + pr] = cn;
            C.sh_cond2[1 * CSTR + pr] = cn;
        }
        if (C.s_valid) {
            float* o = osec + ((size_t)b * Tt + s) * 15;
#pragma unroll
            for (int k = 0; k < 5; k++) {
                o[k] = am[k]; o[5 + k] = mu[k]; o[10 + k] = sg[k];
            }
        }
    }
}

// ---------------------------------------------------------------------------
__global__ __launch_bounds__(256) void precompute_kernel(
    const float* __restrict__ state_h,
    const float* __restrict__ W_my, const float* __restrict__ b_my,
    const float* __restrict__ W_ff, const float* __restrict__ b_ff,
    const float* __restrict__ U_my, const float* __restrict__ U_ff,
    const float* __restrict__ Wh_my, const float* __restrict__ Wh_ff)
{
    const int t = threadIdx.x;
    {
        int gidx = blockIdx.x * 256 + t;
        if (gidx < Hh * NG) {
            int k = gidx >> 9;
            int r = gidx & 511;
            int j = r >> 2, g = r & 3;
            g_Ut_my[gidx] = U_my[(size_t)k * NG + g * 128 + j];
            g_Ut_ff[gidx] = U_ff[(size_t)k * NG + g * 128 + j];
        }
        if (gidx < 75 * Hh) {
            int c = gidx >> 7, k = gidx & 127;
            g_Wht[gidx] = (c < 45) ? Wh_my[(size_t)k * 45 + c]
                                   : Wh_ff[(size_t)k * 30 + (c - 45)];
        }
    }

    __shared__ float hsh[Hh * PRE_BB];
    const int b0 = blockIdx.x * PRE_BB;
    for (int idx = t; idx < Hh * PRE_BB; idx += 256) {
        int k = idx / PRE_BB, bb = idx % PRE_BB;
        hsh[idx] = state_h[(size_t)(b0 + bb) * Hh + k];
    }
    __syncthreads();

    const int c0 = 2 * t;
    u64 accm[PRE_BB], accf[PRE_BB];
    u64 bm = pack2f(b_my[c0], b_my[c0 + 1]);
    u64 bf = pack2f(b_ff[c0], b_ff[c0 + 1]);
#pragma unroll
    for (int bb = 0; bb < PRE_BB; bb++) { accm[bb] = bm; accf[bb] = bf; }

    for (int k = 0; k < Hh; k++) {
        u64 wm = *(const u64*)&W_my[(size_t)k * NG + c0];
        u64 wf = *(const u64*)&W_ff[(size_t)k * NG + c0];
#pragma unroll
        for (int bb = 0; bb < PRE_BB; bb++) {
            u64 hh = dup2f(hsh[k * PRE_BB + bb]);
            fma2(accm[bb], hh, wm);
            fma2(accf[bb], hh, wf);
        }
    }
#pragma unroll
    for (int bb = 0; bb < PRE_BB; bb++) {
        int b = b0 + bb;
        size_t base = ((size_t)(b >> 1) * NG) * 2 + (b & 1);
        float v0, v1;
        unpack2(accm[bb], v0, v1);
        g_encW_my[base + 2 * (size_t)c0] = v0;
        g_encW_my[base + 2 * (size_t)(c0 + 1)] = v1;
        unpack2(accf[bb], v0, v1);
        g_encW_ff[base + 2 * (size_t)c0] = v0;
        g_encW_ff[base + 2 * (size_t)(c0 + 1)] = v1;
    }
}

// ---------------------------------------------------------------------------
// One LSTM phase. Band-local chunk sync; full barrier only post-loop.
// SAMP (my): ch0 runs sampling(t-1)+prefetch(t); cond-tail post-loop.
// !SAMP (ff): cond-tail hidden at ch1 (cond writes ordered by my's post-loop).
// ---------------------------------------------------------------------------
template <int NQ, bool SAMP>
__device__ __forceinline__ void lstm_phase(
    const float* __restrict__ encW,
    const float* __restrict__ Ut,
    const float* __restrict__ Wg,
    const float* __restrict__ pre_src,
    const float* sh_cond, float* sh_h, float* sh_U,
    float (&c)[14], int j, int rphys, const int* epair,
    int band, int boff, int ib, int rot,
    const SampCtx* sc, int t)
{
    u64 acc[4][7];

#pragma unroll
    for (int ch = 0; ch < NCHUNK; ch++) {
        const int pch = (ch + rot) & (NCHUNK - 1);
        cp_wait<0>();
        band_bar(band);    // band's slice of chunk ch visible; band past ch-1
        if (ch + 1 < NCHUNK) {
            stage_band(sh_U + ((ch + 1) & 1) * KCH * NG,
                       Ut + (size_t)((ch + 1 + rot) & (NCHUNK - 1)) * KCH * NG,
                       boff, ib);
        } else {
            stage_band(sh_U + ((ch + 1) & 1) * KCH * NG,
                       pre_src + (size_t)rot * KCH * NG, boff, ib);
        }
        if (ch == 0) {
            if (SAMP) {
                if (t > 0) sample_exec(*sc, t - 1);
                prefetch_exec(*sc, t);
            }
#pragma unroll
            for (int g4 = 0; g4 < 4; g4++) {
                const int col = g4 * 128 + j;
#pragma unroll
                for (int p = 0; p < 7; p++)
                    acc[g4][p] = *(const u64*)&encW[((size_t)epair[p] * NG + col) * 2];
            }
        }
        if (!SAMP && ch == 1) {
#pragma unroll
            for (int q = 0; q < NQ; q++) {
                u64 cpp[7];
#pragma unroll
                for (int p = 0; p < 7; p++)
                    cpp[p] = *(const u64*)(sh_cond + q * CSTR + rphys + 2 * p);
#pragma unroll
                for (int g4 = 0; g4 < 4; g4++) {
                    u64 wd = dup2f(__ldg(&Wg[(size_t)(Hh + q) * NG + g4 * 128 + j]));
#pragma unroll
                    for (int p = 0; p < 7; p++) fma2(acc[g4][p], cpp[p], wd);
                }
            }
        }
        const float* ub = sh_U + (ch & 1) * KCH * NG + 4 * j;
        const float* hb = sh_h + (pch * KCH) * HSTR + rphys;
#pragma unroll
        for (int kk = 0; kk < KCH; kk++) {
            float4 uu = *(const float4*)(ub + kk * NG);
            u64 u0 = dup2f(uu.x);
            u64 u1 = dup2f(uu.y);
            u64 u2 = dup2f(uu.z);
            u64 u3 = dup2f(uu.w);
            const float* hk = hb + kk * HSTR;
            ulonglong2 h01 = *(const ulonglong2*)(hk);
            ulonglong2 h23 = *(const ulonglong2*)(hk + 4);
            ulonglong2 h45 = *(const ulonglong2*)(hk + 8);
            u64 h6 = *(const u64*)(hk + 12);
            u64 hp[7] = { h01.x, h01.y, h23.x, h23.y, h45.x, h45.y, h6 };
#pragma unroll
            for (int p = 0; p < 7; p++) {
                u64 h2 = hp[p];
                fma2(acc[0][p], h2, u0);
                fma2(acc[1][p], h2, u1);
                fma2(acc[2][p], h2, u2);
                fma2(acc[3][p], h2, u3);
            }
        }
    }
    __syncthreads();  // FULL: old-h reads done; sampling's cond writes visible

    if (SAMP) {
        // cond-tail for my phase (after full barrier -> fresh cond visible)
#pragma unroll
        for (int q = 0; q < NQ; q++) {
            u64 cpp[7];
#pragma unroll
            for (int p = 0; p < 7; p++)
                cpp[p] = *(const u64*)(sh_cond + q * CSTR + rphys + 2 * p);
#pragma unroll
            for (int g4 = 0; g4 < 4; g4++) {
                u64 wd = dup2f(__ldg(&Wg[(size_t)(Hh + q) * NG + g4 * 128 + j]));
#pragma unroll
                for (int p = 0; p < 7; p++) fma2(acc[g4][p], cpp[p], wd);
            }
        }
    }

    // ---- gates; c register-private; HW tanh ----
#pragma unroll
    for (int p = 0; p < 7; p++) {
        float zi0, zi1, zf0, zf1, zg0, zg1, zo0, zo1;
        unpack2(acc[0][p], zi0, zi1);
        unpack2(acc[1][p], zf0, zf1);
        unpack2(acc[2][p], zg0, zg1);
        unpack2(acc[3][p], zo0, zo1);
        float c20 = sigf(zf0) * c[2 * p]     + sigf(zi0) * tanh_hw(zg0);
        float c21 = sigf(zf1) * c[2 * p + 1] + sigf(zi1) * tanh_hw(zg1);
        c[2 * p] = c20; c[2 * p + 1] = c21;
        *(u64*)(sh_h + j * HSTR + rphys + 2 * p) =
            pack2f(sigf(zo0) * tanh_hw(c20), sigf(zo1) * tanh_hw(c21));
    }
}

// ---------------------------------------------------------------------------
__global__ __launch_bounds__(NTHREADS, 1) void decoder_kernel(
    const float* __restrict__ cond_m, const float* __restrict__ cond_y,
    const float* __restrict__ cond_f, const float* __restrict__ cond_fa,
    const float* __restrict__ state_h, const float* __restrict__ state_c,
    const float* __restrict__ W_my, const float* __restrict__ W_ff,
    const float* __restrict__ bh_my, const float* __restrict__ bh_ff,
    const float* __restrict__ gumbel, const float* __restrict__ znorm,
    float* __restrict__ out)
{
    extern __shared__ float smem[];
    float* sh_U     = smem;                       // 2*KCH*NG
    float* sh_h_my  = sh_U + 2 * KCH * NG;
    float* sh_h_ff  = sh_h_my + Hh * HSTR;
    float* sh_cond5 = sh_h_ff + Hh * HSTR;
    float* sh_cond2 = sh_cond5 + 5 * CSTR;
    float* sh_r     = sh_cond2 + 2 * CSTR;
    float* scratch  = sh_r + ROWS * 76;

    const int tid = threadIdx.x;
    const int rowbase = blockIdx.x * ROWS;
    const int rot = blockIdx.x & (NCHUNK - 1);
    const int j = tid & 127;
    const int g = tid >> 7;
    const int rlog = g * 14;
    const int rphys = g * 16;
    const int band = (tid >> 5) & 3;
    const int boff = band * 128;
    const int ib = ((tid >> 7) << 5) | (tid & 31);   // 0..127 within band

    // ---- init h and cond ----
    for (int idx = tid; idx < Hh * ROWS; idx += NTHREADS) {
        int k = idx / ROWS, row = idx % ROWS;
        int b = min(rowbase + row, Bsz - 1);
        float hv = state_h[(size_t)b * Hh + k];
        int pr = physrow(row);
        sh_h_my[k * HSTR + pr] = hv;
        sh_h_ff[k * HSTR + pr] = hv;
    }
    if (tid < ROWS) {
        int row = tid;
        int pr = physrow(row);
        int b = min(rowbase + row, Bsz - 1);
        float m0 = cond_m[((size_t)b * Tt) * 2 + 0];
        float m1 = cond_m[((size_t)b * Tt) * 2 + 1];
        float y0 = cond_y[(size_t)b * Tt];
        float f0 = cond_f[(size_t)b * Tt];
        float a0 = cond_fa[(size_t)b * Tt];
        sh_cond5[0 * CSTR + pr] = m0;
        sh_cond5[1 * CSTR + pr] = m1;
        sh_cond5[2 * CSTR + pr] = y0;
        sh_cond5[3 * CSTR + pr] = f0;
        sh_cond5[4 * CSTR + pr] = a0;
        sh_cond2[0 * CSTR + pr] = f0;
        sh_cond2[1 * CSTR + pr] = a0;
    }

    float cmy[14], cff[14];
    int epair[7];
#pragma unroll
    for (int r = 0; r < 14; r++) {
        int b = min(rowbase + rlog + r, Bsz - 1);
        float cv = state_c[(size_t)b * Hh + j];
        cmy[r] = cv; cff[r] = cv;
    }
#pragma unroll
    for (int p = 0; p < 7; p++)
        epair[p] = min(rowbase + rlog + 2 * p, Bsz - 2) >> 1;

    // heads (R12 form): 300 active threads, c=tid%75, q=tid/75
    const int hc = tid % 75;
    const int hq = tid / 75;
    const bool hact = tid < 300;
    float hbias = 0.0f;
    if (hact) hbias = (hc < 45) ? bh_my[hc] : bh_ff[hc - 45];

    SampCtx ctx;
    ctx.cond_m = cond_m; ctx.cond_y = cond_y; ctx.cond_f = cond_f;
    ctx.cond_fa = cond_fa; ctx.gumbel = gumbel; ctx.znorm = znorm;
    ctx.out_gm = out;
    ctx.out_gy = out + (size_t)Bsz * Tt * 30;
    ctx.out_gf = out + (size_t)Bsz * Tt * 45;
    ctx.out_gfa = out + (size_t)Bsz * Tt * 60;
    ctx.sh_r = sh_r; ctx.sh_cond5 = sh_cond5; ctx.sh_cond2 = sh_cond2;
    ctx.scratch = scratch;
    ctx.s_row = tid >> 2;
    ctx.s_d = tid & 3;
    ctx.s_act = tid < 4 * ROWS;
    ctx.s_b = ctx.s_act ? min(rowbase + ctx.s_row, Bsz - 1) : 0;
    ctx.s_valid = ctx.s_act && (rowbase + ctx.s_row) < Bsz;
    ctx.s_pr = physrow(min(ctx.s_row, ROWS - 1));
    ctx.sbase = tid * 9;

    __syncthreads();

    // stage my chunk `rot` (band slice) for step 0
    stage_band(sh_U, g_Ut_my + (size_t)rot * KCH * NG, boff, ib);

    for (int t = 0; t < Tt; t++) {
        lstm_phase<5, true>(g_encW_my, g_Ut_my, W_my, g_Ut_ff,
                            sh_cond5, sh_h_my, sh_U, cmy, j, rphys, epair,
                            band, boff, ib, rot, &ctx, t);
        lstm_phase<2, false>(g_encW_ff, g_Ut_ff, W_ff, g_Ut_my,
                             sh_cond2, sh_h_ff, sh_U, cff, j, rphys, epair,
                             band, boff, ib, rot, &ctx, t);
        __syncthreads();  // D: h_my / h_ff visible for heads

        if (hact) {
            const float* hb = ((hc < 45) ? sh_h_my : sh_h_ff) + hq * 16;
            const float4* wr = (const float4*)(g_Wht + hc * Hh);
            u64 a[7];
            u64 binit = dup2f(hbias);
#pragma unroll
            for (int p = 0; p < 7; p++) a[p] = binit;
#pragma unroll 4
            for (int k4 = 0; k4 < Hh / 4; k4++) {
                float4 w4 = __ldg(&wr[k4]);
                float wv[4] = { w4.x, w4.y, w4.z, w4.w };
#pragma unroll
                for (int kk = 0; kk < 4; kk++) {
                    const float* hk = hb + (4 * k4 + kk) * HSTR;
                    ulonglong2 h01 = *(const ulonglong2*)(hk);
                    ulonglong2 h23 = *(const ulonglong2*)(hk + 4);
                    ulonglong2 h45 = *(const ulonglong2*)(hk + 8);
                    u64 h6 = *(const u64*)(hk + 12);
                    u64 wd = dup2f(wv[kk]);
                    fma2(a[0], h01.x, wd);
                    fma2(a[1], h01.y, wd);
                    fma2(a[2], h23.x, wd);
                    fma2(a[3], h23.y, wd);
                    fma2(a[4], h45.x, wd);
                    fma2(a[5], h45.y, wd);
                    fma2(a[6], h6, wd);
                }
            }
#pragma unroll
            for (int p = 0; p < 7; p++) {
                float v0, v1;
                unpack2(a[p], v0, v1);
                int row = hq * 14 + 2 * p;
                sh_r[row * 76 + hc] = v0;
                sh_r[(row + 1) * 76 + hc] = v1;
            }
        }
        __syncthreads();  // A: sh_r visible for next step's my-ch0 sampling
    }

    sample_exec(ctx, Tt - 1);
}

// ---------------------------------------------------------------------------
extern "C" void kernel_launch(void* const* d_in, const int* in_sizes, int n_in,
                              void* d_out, int out_size)
{
    (void)in_sizes; (void)n_in; (void)out_size;
    const float* cond_m  = (const float*)d_in[0];
    const float* cond_y  = (const float*)d_in[1];
    const float* cond_f  = (const float*)d_in[2];
    const float* cond_fa = (const float*)d_in[3];
    const float* state_h = (const float*)d_in[4];
    const float* state_c = (const float*)d_in[5];
    const float* W_my    = (const float*)d_in[6];
    const float* U_my    = (const float*)d_in[7];
    const float* b_my    = (const float*)d_in[8];
    const float* W_ff    = (const float*)d_in[9];
    const float* U_ff    = (const float*)d_in[10];
    const float* b_ff    = (const float*)d_in[11];
    const float* Wh_my   = (const float*)d_in[12];
    const float* bh_my   = (const float*)d_in[13];
    const float* Wh_ff   = (const float*)d_in[14];
    const float* bh_ff   = (const float*)d_in[15];
    const float* gumbel  = (const float*)d_in[16];
    const float* znorm   = (const float*)d_in[17];
    float* out = (float*)d_out;

    const int smem_floats = 2 * KCH * NG + 2 * Hh * HSTR + 7 * CSTR + ROWS * 76
                            + 4 * ROWS * 9;
    const int smem_bytes = smem_floats * (int)sizeof(float);  // 227584 B

    cudaFuncSetAttribute(decoder_kernel,
                         cudaFuncAttributeMaxDynamicSharedMemorySize, smem_bytes);

    precompute_kernel<<<Bsz / PRE_BB, 256>>>(state_h, W_my, b_my, W_ff, b_ff,
                                             U_my, U_ff, Wh_my, Wh_ff);
    decoder_kernel<<<NCTA, NTHREADS, smem_bytes>>>(
        cond_m, cond_y, cond_f, cond_fa, state_h, state_c,
        W_my, W_ff, bh_my, bh_ff, gumbel, znorm, out);
}